// round 14
// baseline (speedup 1.0000x reference)
#include <cuda_runtime.h>
#include <cuda_fp16.h>
#include <cstdint>

#define NSTATES 512
#define MSYMS   256
#define BATCHN  256
#define TLEN    256

#define GB 16                // batch groups (clusters)
#define GI 4                 // cluster size (i-slices)
#define NBg 16               // batch rows per group
#define MI 128               // states per CTA
#define NCTA (GB*GI)         // 64 CTAs
#define NT 256               // 8 warps

#define ESTR 520             // fp16 row stride (1040B)

// ---- dynamic SMEM layout (bytes) ----
#define BUF_OFF    0                     // 8 tiles x 16 x 18 floats = 9216
#define SM_M_OFF   9216                  // float [2][16][4] = 512
#define SM_S_OFF   9728                  // float [2][16][4] = 512
#define P_OFF      10240                 // 128 x 1040 = 133120
#define E_OFF      143360                // 16 x 1040 = 16640
#define SYMS_OFF   160000                // 16 x 256 int = 16384
#define OUT_OFF    176384                // float [16][256] = 16384
#define SMEM_TOTAL 192768

// ---------------- device globals ----------------
__device__ __half gPh[NSTATES * NSTATES];   // column-softmax of transition, fp16
__device__ float  gET[MSYMS * NSTATES];     // emission PROBS transposed [sym][state]
__device__ float  gPr[NSTATES];             // prior PROBS
__device__ __half gEh[2][BATCHN][NSTATES];  // scaled E, fp16, dbl-buffered

// ---------------- PTX helpers ----------------
__device__ __forceinline__ uint32_t smem_u32(const void* p) {
    uint32_t a;
    asm("{ .reg .u64 t; cvta.to.shared.u64 t, %1; cvt.u32.u64 %0, t; }" : "=r"(a) : "l"(p));
    return a;
}
__device__ __forceinline__ uint32_t cluster_rank() {
    uint32_t r; asm("mov.u32 %0, %%cluster_ctarank;" : "=r"(r)); return r;
}
#define CLUSTER_ARRIVE() asm volatile("barrier.cluster.arrive.aligned;" ::: "memory")
#define CLUSTER_WAIT()   asm volatile("barrier.cluster.wait.aligned;"   ::: "memory")

// push (m,s) into peer rank's sm_m / sm_s (sm_s = sm_m + 512B)
__device__ __forceinline__ void dsmem_st_ms(uint32_t laddr_m, uint32_t rank, float mx, float sx) {
    asm volatile(
        "{\n\t.reg .b32 r;\n\t"
        "mapa.shared::cluster.u32 r, %0, %1;\n\t"
        "st.shared::cluster.f32 [r], %2;\n\t"
        "st.shared::cluster.f32 [r+512], %3;\n\t}"
        :: "r"(laddr_m), "r"(rank), "f"(mx), "f"(sx) : "memory");
}
__device__ __forceinline__ void ldsm4(uint32_t& r0, uint32_t& r1, uint32_t& r2, uint32_t& r3,
                                      uint32_t addr) {
    asm volatile("ldmatrix.sync.aligned.m8n8.x4.shared.b16 {%0,%1,%2,%3}, [%4];"
                 : "=r"(r0), "=r"(r1), "=r"(r2), "=r"(r3) : "r"(addr));
}
__device__ __forceinline__ void mma16816(float& d0, float& d1, float& d2, float& d3,
                                         uint32_t a0, uint32_t a1, uint32_t a2, uint32_t a3,
                                         uint32_t b0, uint32_t b1) {
    asm volatile(
        "mma.sync.aligned.m16n8k16.row.col.f32.f16.f16.f32 "
        "{%0,%1,%2,%3}, {%4,%5,%6,%7}, {%8,%9}, {%0,%1,%2,%3};"
        : "+f"(d0), "+f"(d1), "+f"(d2), "+f"(d3)
        : "r"(a0), "r"(a1), "r"(a2), "r"(a3), "r"(b0), "r"(b1));
}

// ---------------- fused prep kernel ----------------
__global__ void k_prep(const float* __restrict__ em, const float* __restrict__ tr,
                       const float* __restrict__ pr) {
    __shared__ float red[256];
    const int blk = blockIdx.x, t = threadIdx.x;

    if (blk < NSTATES) {
        float x = em[blk * MSYMS + t];
        red[t] = x; __syncthreads();
        for (int s = 128; s > 0; s >>= 1) { if (t < s) red[t] = fmaxf(red[t], red[t + s]); __syncthreads(); }
        float m = red[0]; __syncthreads();
        float e = __expf(x - m);
        red[t] = e; __syncthreads();
        for (int s = 128; s > 0; s >>= 1) { if (t < s) red[t] += red[t + s]; __syncthreads(); }
        gET[t * NSTATES + blk] = __fdividef(e, red[0]);
        __syncthreads();

        float x0 = tr[t * NSTATES + blk];
        float x1 = tr[(t + 256) * NSTATES + blk];
        red[t] = fmaxf(x0, x1); __syncthreads();
        for (int s = 128; s > 0; s >>= 1) { if (t < s) red[t] = fmaxf(red[t], red[t + s]); __syncthreads(); }
        float mm = red[0]; __syncthreads();
        red[t] = __expf(x0 - mm) + __expf(x1 - mm); __syncthreads();
        for (int s = 128; s > 0; s >>= 1) { if (t < s) red[t] += red[t + s]; __syncthreads(); }
        float clse = mm + __logf(red[0]);
        gPh[t * NSTATES + blk]         = __float2half_rn(__expf(x0 - clse));
        gPh[(t + 256) * NSTATES + blk] = __float2half_rn(__expf(x1 - clse));
    } else {
        float x0 = pr[t], x1 = pr[t + 256];
        red[t] = fmaxf(x0, x1); __syncthreads();
        for (int s = 128; s > 0; s >>= 1) { if (t < s) red[t] = fmaxf(red[t], red[t + s]); __syncthreads(); }
        float m = red[0]; __syncthreads();
        float e0 = __expf(x0 - m), e1 = __expf(x1 - m);
        red[t] = e0 + e1; __syncthreads();
        for (int s = 128; s > 0; s >>= 1) { if (t < s) red[t] += red[t + s]; __syncthreads(); }
        float inv = __fdividef(1.f, red[0]);
        gPr[t]       = e0 * inv;
        gPr[t + 256] = e1 * inv;
    }
}

// ---------------- forward kernel (4-CTA clusters, 16 batch rows/group) ----------------
extern __shared__ char sm_raw[];

__global__ void __launch_bounds__(NT, 1) forward_kernel(const int* __restrict__ batch,
                                                        float* __restrict__ out) {
    char* sm = sm_raw;
    const uint32_t smem_base = smem_u32(sm);
    float* buf    = (float*)(sm + BUF_OFF);
    int*   syms   = (int*)(sm + SYMS_OFF);    // [16][256]
    float* sm_out = (float*)(sm + OUT_OFF);   // [16][256]
    const uint32_t P_base = smem_base + P_OFF;
    const uint32_t E_base = smem_base + E_OFF;
    const uint32_t SMM    = smem_base + SM_M_OFF;

    const int tid  = threadIdx.x;
    const int lane = tid & 31;
    const int w    = tid >> 5;               // warp = m-tile; owns batch rows w, w+8
    const int g    = blockIdx.x >> 2;        // 0..15 batch group
    const int j    = (int)cluster_rank();    // 0..3 i-slice
    const int gb0  = g * NBg + w;
    const int gb1  = gb0 + 8;

    // ---------------- prologue ----------------
    #pragma unroll
    for (int it = 0; it < 32; it++) {
        int idx = tid + NT * it;              // 16B chunks of P
        int row = idx >> 6, c = idx & 63;
        *(uint4*)(sm + P_OFF + row * (ESTR * 2) + c * 16) =
            *(const uint4*)(&gPh[(j * MI + row) * NSTATES] + c * 8);
    }
    for (int idx = tid; idx < NBg * TLEN; idx += NT)
        syms[idx] = batch[(g * NBg + (idx >> 8)) * TLEN + (idx & 255)];
    __syncthreads();

    // A fragments resident in registers: warp w = m-tile w, full K=512
    uint32_t a[32][4];
    {
        const int arow  = w * 16 + (lane & 15);
        const int akoff = (lane >> 4) * 8;
        #pragma unroll
        for (int kk = 0; kk < 32; kk++) {
            uint32_t addr = P_base + (uint32_t)((arow * ESTR + kk * 16 + akoff) * 2);
            ldsm4(a[kk][0], a[kk][1], a[kk][2], a[kk][3], addr);
        }
    }
    // B ldmatrix x4 addresses: set0 = rows 0-7, set1 = rows 8-15
    const uint32_t b_addr0 = E_base + (uint32_t)(((lane & 7) * ESTR + (lane >> 3) * 8) * 2);
    const uint32_t b_addr1 = b_addr0 + (uint32_t)(8 * ESTR * 2);

    // ---------------- step 0 (prob space), both rows ----------------
    {
        #pragma unroll
        for (int half = 0; half < 2; half++) {
            int r = w + 8 * half, gb = g * NBg + r;
            int sy = syms[r * TLEN + 0];
            float4 et = *(const float4*)&gET[sy * NSTATES + j * MI + lane * 4];
            float4 pp = *(const float4*)&gPr[j * MI + lane * 4];
            float t0 = et.x * pp.x, t1 = et.y * pp.y, t2 = et.z * pp.z, t3 = et.w * pp.w;
            float tm = fmaxf(fmaxf(t0, t1), fmaxf(t2, t3));
            float sr = (t0 + t1) + (t2 + t3);
            #pragma unroll
            for (int o = 16; o > 0; o >>= 1) {
                tm = fmaxf(tm, __shfl_xor_sync(0xffffffffu, tm, o));
                sr += __shfl_xor_sync(0xffffffffu, sr, o);
            }
            float rr = __fdividef(1.f, tm);
            union { __half2 h[2]; uint2 uu; } cv;
            cv.h[0] = __floats2half2_rn(t0 * rr, t1 * rr);
            cv.h[1] = __floats2half2_rn(t2 * rr, t3 * rr);
            __stcg((uint2*)&gEh[0][gb][j * MI + lane * 4], cv.uu);
            if (lane == 0) {
                float mpub = __logf(tm), spub = sr * rr;
                uint32_t la = SMM + (0 * 16 + r) * 16 + j * 4;
                #pragma unroll
                for (int rk = 0; rk < GI; rk++) dsmem_st_ms(la, (uint32_t)rk, mpub, spub);
            }
        }
        CLUSTER_ARRIVE();
    }

    // ---------------- main loop ----------------
    for (int t = 1; t < TLEN; ++t) {
        const int p = (t - 1) & 1, q = t & 1;

        // prefetch (peer-independent) before the wait
        int sy0 = syms[(w)     * TLEN + t];
        int sy1 = syms[(w + 8) * TLEN + t];
        float4 et0 = *(const float4*)&gET[sy0 * NSTATES + j * MI + lane * 4];
        float4 et1 = *(const float4*)&gET[sy1 * NSTATES + j * MI + lane * 4];

        CLUSTER_WAIT();

        // E raw loads (L2) — issue all four first
        const __half* es0 = &gEh[p][gb0][0];
        const __half* es1 = &gEh[p][gb1][0];
        uint4 e00 = __ldcg((const uint4*)(es0 + lane * 8));
        uint4 e01 = __ldcg((const uint4*)(es0 + (lane + 32) * 8));
        uint4 e10 = __ldcg((const uint4*)(es1 + lane * 8));
        uint4 e11 = __ldcg((const uint4*)(es1 + (lane + 32) * 8));

        // stats for both rows (16B LDS each)
        float4 mv0 = *(float4*)(sm + SM_M_OFF + p * 256 + (w)     * 16);
        float4 mv1 = *(float4*)(sm + SM_M_OFF + p * 256 + (w + 8) * 16);
        float ml0 = fmaxf(fmaxf(mv0.x, mv0.y), fmaxf(mv0.z, mv0.w));
        float ml1 = fmaxf(fmaxf(mv1.x, mv1.y), fmaxf(mv1.z, mv1.w));
        float sca0 = __expf(((lane >> 4) ? mv0.y : mv0.x) - ml0);
        float scb0 = __expf(((lane >> 4) ? mv0.w : mv0.z) - ml0);
        float sca1 = __expf(((lane >> 4) ? mv1.y : mv1.x) - ml1);
        float scb1 = __expf(((lane >> 4) ? mv1.w : mv1.z) - ml1);

        // out column t-1 (redundant on all CTAs, lane0, hidden under ldcg)
        if (lane == 0) {
            float4 sv0 = *(float4*)(sm + SM_S_OFF + p * 256 + (w)     * 16);
            float4 sv1 = *(float4*)(sm + SM_S_OFF + p * 256 + (w + 8) * 16);
            float ps0 = sca0 * sv0.x + __expf(mv0.y - ml0) * sv0.y
                      + scb0 * sv0.z + __expf(mv0.w - ml0) * sv0.w;
            float ps1 = sca1 * sv1.x + __expf(mv1.y - ml1) * sv1.y
                      + scb1 * sv1.z + __expf(mv1.w - ml1) * sv1.w;
            sm_out[(w)     * 256 + (t - 1)] = ml0 + __logf(ps0);
            sm_out[(w + 8) * 256 + (t - 1)] = ml1 + __logf(ps1);
        }

        // stage scaled E rows w and w+8
        {
            char* ed0 = sm + E_OFF + (w)     * (ESTR * 2);
            char* ed1 = sm + E_OFF + (w + 8) * (ESTR * 2);
            __half2 ha0 = __half2half2(__float2half_rn(sca0));
            __half2 hb0 = __half2half2(__float2half_rn(scb0));
            __half2 ha1 = __half2half2(__float2half_rn(sca1));
            __half2 hb1 = __half2half2(__float2half_rn(scb1));
            __half2* p00 = (__half2*)&e00; __half2* p01 = (__half2*)&e01;
            __half2* p10 = (__half2*)&e10; __half2* p11 = (__half2*)&e11;
            #pragma unroll
            for (int z = 0; z < 4; z++) {
                p00[z] = __hmul2(p00[z], ha0); p01[z] = __hmul2(p01[z], hb0);
                p10[z] = __hmul2(p10[z], ha1); p11[z] = __hmul2(p11[z], hb1);
            }
            *(uint4*)(ed0 + lane * 16)        = e00;
            *(uint4*)(ed0 + (lane + 32) * 16) = e01;
            *(uint4*)(ed1 + lane * 16)        = e10;
            *(uint4*)(ed1 + (lane + 32) * 16) = e11;
        }
        __syncthreads();

        // HMMA: m16 x n16 x K512 — 4 independent accumulator chains
        float aA0=0,aA1=0,aA2=0,aA3=0, aB0=0,aB1=0,aB2=0,aB3=0;   // cols 0-7
        float aC0=0,aC1=0,aC2=0,aC3=0, aD0=0,aD1=0,aD2=0,aD3=0;   // cols 8-15
        #pragma unroll
        for (int kk = 0; kk < 32; kk += 2) {
            uint32_t b0, b1, c0, c1, d0, d1, e0, e1;
            ldsm4(b0, b1, c0, c1, b_addr0 + (uint32_t)(kk * 32));
            ldsm4(d0, d1, e0, e1, b_addr1 + (uint32_t)(kk * 32));
            mma16816(aA0, aA1, aA2, aA3, a[kk][0], a[kk][1], a[kk][2], a[kk][3], b0, b1);
            mma16816(aC0, aC1, aC2, aC3, a[kk][0], a[kk][1], a[kk][2], a[kk][3], d0, d1);
            mma16816(aB0, aB1, aB2, aB3, a[kk+1][0], a[kk+1][1], a[kk+1][2], a[kk+1][3], c0, c1);
            mma16816(aD0, aD1, aD2, aD3, a[kk+1][0], a[kk+1][1], a[kk+1][2], a[kk+1][3], e0, e1);
        }

        // stash m-tile partials: buf[w] is 16 state-rows x 18 cols
        {
            float* bw = &buf[w * 288];
            int rr = lane >> 2, c = (lane & 3) * 2;
            *(float2*)&bw[rr * 18 + c]           = make_float2(aA0 + aB0, aA1 + aB1);
            *(float2*)&bw[(rr + 8) * 18 + c]     = make_float2(aA2 + aB2, aA3 + aB3);
            *(float2*)&bw[rr * 18 + c + 8]       = make_float2(aC0 + aD0, aC1 + aD1);
            *(float2*)&bw[(rr + 8) * 18 + c + 8] = make_float2(aC2 + aD2, aC3 + aD3);
        }
        __syncthreads();

        // epilogue (prob space), both rows
        {
            int til = lane >> 2, rb = (lane & 3) * 4;
            #pragma unroll
            for (int half = 0; half < 2; half++) {
                int r = w + 8 * half, gb = half ? gb1 : gb0;
                float4 et = half ? et1 : et0;
                float mloc = half ? ml1 : ml0;
                const float* bp = &buf[til * 288 + r];
                float t0 = bp[(rb + 0) * 18] * et.x;
                float t1 = bp[(rb + 1) * 18] * et.y;
                float t2 = bp[(rb + 2) * 18] * et.z;
                float t3 = bp[(rb + 3) * 18] * et.w;
                float tm = fmaxf(fmaxf(t0, t1), fmaxf(t2, t3));
                float sr = (t0 + t1) + (t2 + t3);
                #pragma unroll
                for (int o = 16; o > 0; o >>= 1) {
                    tm = fmaxf(tm, __shfl_xor_sync(0xffffffffu, tm, o));
                    sr += __shfl_xor_sync(0xffffffffu, sr, o);
                }
                float rcp = __fdividef(1.f, tm);
                union { __half2 h[2]; uint2 uu; } cv;
                cv.h[0] = __floats2half2_rn(t0 * rcp, t1 * rcp);
                cv.h[1] = __floats2half2_rn(t2 * rcp, t3 * rcp);
                __stcg((uint2*)&gEh[q][gb][j * MI + lane * 4], cv.uu);
                if (lane == 0) {
                    float mpub = mloc + __logf(tm), spub = sr * rcp;
                    uint32_t la = SMM + (q * 16 + r) * 16 + j * 4;
                    #pragma unroll
                    for (int rk = 0; rk < GI; rk++) dsmem_st_ms(la, (uint32_t)rk, mpub, spub);
                }
            }
        }

        CLUSTER_ARRIVE();
    }

    // final column + flush (j == 3 owns the output write)
    CLUSTER_WAIT();
    if (j == 3) {
        if (tid < NBg) {
            float4 mv = *(float4*)(sm + SM_M_OFF + 256 + tid * 16);
            float4 sv = *(float4*)(sm + SM_S_OFF + 256 + tid * 16);
            float mb = fmaxf(fmaxf(mv.x, mv.y), fmaxf(mv.z, mv.w));
            float ss = __expf(mv.x - mb) * sv.x + __expf(mv.y - mb) * sv.y
                     + __expf(mv.z - mb) * sv.z + __expf(mv.w - mb) * sv.w;
            sm_out[tid * 256 + 255] = mb + __logf(ss);
        }
        __syncthreads();
        #pragma unroll
        for (int half = 0; half < 2; half++) {
            int gb = half ? gb1 : gb0;
            const float4* orow = (const float4*)(sm_out + (w + 8 * half) * 256);
            float4* dst = (float4*)&out[gb * TLEN];
            #pragma unroll
            for (int z = 0; z < 2; z++) dst[lane + 32 * z] = orow[lane + 32 * z];
        }
    }
}

// ---------------- launch ----------------
extern "C" void kernel_launch(void* const* d_in, const int* in_sizes, int n_in,
                              void* d_out, int out_size) {
    const int*   batch = (const int*)d_in[0];
    const float* em    = (const float*)d_in[1];
    const float* tr    = (const float*)d_in[2];
    const float* pr    = (const float*)d_in[3];
    float* out = (float*)d_out;

    cudaFuncSetAttribute(forward_kernel, cudaFuncAttributeMaxDynamicSharedMemorySize, SMEM_TOTAL);

    k_prep<<<NSTATES + 1, 256>>>(em, tr, pr);

    cudaLaunchConfig_t cfg = {};
    cfg.gridDim = dim3(NCTA, 1, 1);
    cfg.blockDim = dim3(NT, 1, 1);
    cfg.dynamicSmemBytes = SMEM_TOTAL;
    cfg.stream = 0;
    cudaLaunchAttribute attrs[1];
    attrs[0].id = cudaLaunchAttributeClusterDimension;
    attrs[0].val.clusterDim.x = GI;
    attrs[0].val.clusterDim.y = 1;
    attrs[0].val.clusterDim.z = 1;
    cfg.attrs = attrs;
    cfg.numAttrs = 1;
    cudaLaunchKernelEx(&cfg, forward_kernel, batch, out);
}

// round 16
// speedup vs baseline: 1.4818x; 1.4818x over previous
#include <cuda_runtime.h>
#include <cuda_fp16.h>
#include <cstdint>

#define NSTATES 512
#define MSYMS   256
#define BATCHN  256
#define TLEN    256

#define GB 32                // batch groups (clusters)
#define GI 4                 // cluster size (i-slices)
#define NBg 8                // batch rows per group
#define MI 128               // states per CTA
#define NCTA (GB*GI)         // 128 CTAs
#define NT 256               // 8 warps

#define ESTR 520             // fp16 row stride (1040B)

// ---- dynamic SMEM layout (bytes) ----
#define BUF_OFF    0                     // 8 tiles x 162 floats = 5184
#define SM_M_OFF   5248                  // float [2][8][4] = 256
#define SM_S_OFF   5504                  // float [2][8][4] = 256
#define P_OFF      5760                  // 128 x 520 fp16 = 133120
#define E_OFF      138880                // 8 x 520 fp16 = 8320
#define SYMS_OFF   147200                // 8 x 256 int = 8192
#define OUT_OFF    155392                // float [8][256] = 8192
#define SMEM_TOTAL 163584

// ---------------- device globals ----------------
__device__ __half gPh[NSTATES * NSTATES];   // column-softmax of transition, fp16
__device__ float  gET[MSYMS * NSTATES];     // emission PROBS transposed [sym][state]
__device__ float  gPr[NSTATES];             // prior PROBS
__device__ __half gEh[2][BATCHN][NSTATES];  // scaled E, fp16, dbl-buffered

// ---------------- PTX helpers ----------------
__device__ __forceinline__ uint32_t smem_u32(const void* p) {
    uint32_t a;
    asm("{ .reg .u64 t; cvta.to.shared.u64 t, %1; cvt.u32.u64 %0, t; }" : "=r"(a) : "l"(p));
    return a;
}
__device__ __forceinline__ uint32_t cluster_rank() {
    uint32_t r; asm("mov.u32 %0, %%cluster_ctarank;" : "=r"(r)); return r;
}
#define CLUSTER_ARRIVE() asm volatile("barrier.cluster.arrive.aligned;" ::: "memory")
#define CLUSTER_WAIT()   asm volatile("barrier.cluster.wait.aligned;"   ::: "memory")

__device__ __forceinline__ void dsmem_st_ms(uint32_t laddr_m, uint32_t rank, float mx, float sx) {
    asm volatile(
        "{\n\t.reg .b32 r;\n\t"
        "mapa.shared::cluster.u32 r, %0, %1;\n\t"
        "st.shared::cluster.f32 [r], %2;\n\t"
        "st.shared::cluster.f32 [r+256], %3;\n\t}"
        :: "r"(laddr_m), "r"(rank), "f"(mx), "f"(sx) : "memory");
}
__device__ __forceinline__ void ldsm4(uint32_t& r0, uint32_t& r1, uint32_t& r2, uint32_t& r3,
                                      uint32_t addr) {
    asm volatile("ldmatrix.sync.aligned.m8n8.x4.shared.b16 {%0,%1,%2,%3}, [%4];"
                 : "=r"(r0), "=r"(r1), "=r"(r2), "=r"(r3) : "r"(addr));
}
__device__ __forceinline__ void mma16816(float& d0, float& d1, float& d2, float& d3,
                                         uint32_t a0, uint32_t a1, uint32_t a2, uint32_t a3,
                                         uint32_t b0, uint32_t b1) {
    asm volatile(
        "mma.sync.aligned.m16n8k16.row.col.f32.f16.f16.f32 "
        "{%0,%1,%2,%3}, {%4,%5,%6,%7}, {%8,%9}, {%0,%1,%2,%3};"
        : "+f"(d0), "+f"(d1), "+f"(d2), "+f"(d3)
        : "r"(a0), "r"(a1), "r"(a2), "r"(a3), "r"(b0), "r"(b1));
}

// ---------------- fused prep kernel ----------------
__global__ void k_prep(const float* __restrict__ em, const float* __restrict__ tr,
                       const float* __restrict__ pr) {
    __shared__ float red[256];
    const int blk = blockIdx.x, t = threadIdx.x;

    if (blk < NSTATES) {
        float x = em[blk * MSYMS + t];
        red[t] = x; __syncthreads();
        for (int s = 128; s > 0; s >>= 1) { if (t < s) red[t] = fmaxf(red[t], red[t + s]); __syncthreads(); }
        float m = red[0]; __syncthreads();
        float e = __expf(x - m);
        red[t] = e; __syncthreads();
        for (int s = 128; s > 0; s >>= 1) { if (t < s) red[t] += red[t + s]; __syncthreads(); }
        gET[t * NSTATES + blk] = __fdividef(e, red[0]);
        __syncthreads();

        float x0 = tr[t * NSTATES + blk];
        float x1 = tr[(t + 256) * NSTATES + blk];
        red[t] = fmaxf(x0, x1); __syncthreads();
        for (int s = 128; s > 0; s >>= 1) { if (t < s) red[t] = fmaxf(red[t], red[t + s]); __syncthreads(); }
        float mm = red[0]; __syncthreads();
        red[t] = __expf(x0 - mm) + __expf(x1 - mm); __syncthreads();
        for (int s = 128; s > 0; s >>= 1) { if (t < s) red[t] += red[t + s]; __syncthreads(); }
        float clse = mm + __logf(red[0]);
        gPh[t * NSTATES + blk]         = __float2half_rn(__expf(x0 - clse));
        gPh[(t + 256) * NSTATES + blk] = __float2half_rn(__expf(x1 - clse));
    } else {
        float x0 = pr[t], x1 = pr[t + 256];
        red[t] = fmaxf(x0, x1); __syncthreads();
        for (int s = 128; s > 0; s >>= 1) { if (t < s) red[t] = fmaxf(red[t], red[t + s]); __syncthreads(); }
        float m = red[0]; __syncthreads();
        float e0 = __expf(x0 - m), e1 = __expf(x1 - m);
        red[t] = e0 + e1; __syncthreads();
        for (int s = 128; s > 0; s >>= 1) { if (t < s) red[t] += red[t + s]; __syncthreads(); }
        float inv = __fdividef(1.f, red[0]);
        gPr[t]       = e0 * inv;
        gPr[t + 256] = e1 * inv;
    }
}

// ---------------- forward kernel (4-CTA clusters) ----------------
extern __shared__ char sm_raw[];

__global__ void __launch_bounds__(NT, 1) forward_kernel(const int* __restrict__ batch,
                                                        float* __restrict__ out) {
    char* sm = sm_raw;
    const uint32_t smem_base = smem_u32(sm);
    float* buf    = (float*)(sm + BUF_OFF);
    int*   syms   = (int*)(sm + SYMS_OFF);    // [8][256]
    float* sm_out = (float*)(sm + OUT_OFF);   // [8][256]
    const uint32_t P_base = smem_base + P_OFF;
    const uint32_t E_base = smem_base + E_OFF;
    const uint32_t SMM    = smem_base + SM_M_OFF;

    const int tid  = threadIdx.x;
    const int lane = tid & 31;
    const int w    = tid >> 5;               // warp = m-tile = batch row
    const int g    = blockIdx.x >> 2;        // 0..31 batch group
    const int j    = (int)cluster_rank();    // 0..3 i-slice
    const int gb   = g * NBg + w;            // global batch row for this warp

    // ---------------- prologue ----------------
    #pragma unroll
    for (int it = 0; it < 32; it++) {
        int idx = tid + NT * it;              // 16B chunks
        int row = idx >> 6, c = idx & 63;
        *(uint4*)(sm + P_OFF + row * (ESTR * 2) + c * 16) =
            *(const uint4*)(&gPh[(j * MI + row) * NSTATES] + c * 8);
    }
    for (int idx = tid; idx < NBg * TLEN; idx += NT)
        syms[idx] = batch[(g * NBg + (idx >> 8)) * TLEN + (idx & 255)];
    __syncthreads();

    // A fragments resident in registers: warp w = m-tile w, full K=512
    uint32_t a[32][4];
    {
        const int arow  = w * 16 + (lane & 15);
        const int akoff = (lane >> 4) * 8;
        #pragma unroll
        for (int kk = 0; kk < 32; kk++) {
            uint32_t addr = P_base + (uint32_t)((arow * ESTR + kk * 16 + akoff) * 2);
            ldsm4(a[kk][0], a[kk][1], a[kk][2], a[kk][3], addr);
        }
    }
    // B ldmatrix x4 per-thread address
    const uint32_t b_addr4 = E_base + (uint32_t)(((lane & 7) * ESTR + (lane >> 3) * 8) * 2);

    // ---------------- step 0 (prob space) ----------------
    {
        int sy = syms[w * TLEN + 0];
        float4 et = *(const float4*)&gET[sy * NSTATES + j * MI + lane * 4];
        float4 pp = *(const float4*)&gPr[j * MI + lane * 4];
        float t0 = et.x * pp.x, t1 = et.y * pp.y, t2 = et.z * pp.z, t3 = et.w * pp.w;
        float tm = fmaxf(fmaxf(t0, t1), fmaxf(t2, t3));
        float sr = (t0 + t1) + (t2 + t3);
        #pragma unroll
        for (int o = 16; o > 0; o >>= 1) {
            tm = fmaxf(tm, __shfl_xor_sync(0xffffffffu, tm, o));
            sr += __shfl_xor_sync(0xffffffffu, sr, o);
        }
        float r = __fdividef(1.f, tm);
        float e0 = t0 * r, e1 = t1 * r, e2 = t2 * r, e3 = t3 * r;
        union { __half2 h[2]; uint2 uu; } cv;
        cv.h[0] = __floats2half2_rn(e0, e1);
        cv.h[1] = __floats2half2_rn(e2, e3);
        __stcg((uint2*)&gEh[0][gb][j * MI + lane * 4], cv.uu);
        if (lane == 0) {
            float mpub = __logf(tm);
            float spub = sr * r;
            uint32_t la = SMM + (0 * 8 + w) * 16 + j * 4;
            #pragma unroll
            for (int rr = 0; rr < GI; rr++) dsmem_st_ms(la, (uint32_t)rr, mpub, spub);
        }
        CLUSTER_ARRIVE();
    }

    // ---------------- main loop ----------------
    for (int t = 1; t < TLEN; ++t) {
        const int p = (t - 1) & 1, q = t & 1;

        // prefetch before the wait (emission PROBS for this thread's 4 states)
        int sy = syms[w * TLEN + t];
        float4 et = *(const float4*)&gET[sy * NSTATES + j * MI + lane * 4];

        CLUSTER_WAIT();

        // E raw loads (L2) — issue first, longest latency
        const __half* esrc = &gEh[p][gb][0];
        uint4 er0 = __ldcg((const uint4*)(esrc + lane * 8));
        uint4 er1 = __ldcg((const uint4*)(esrc + (lane + 32) * 8));

        // per-thread stats for row w (16B LDS)
        float4 mv = *(float4*)(sm + SM_M_OFF + p * 128 + w * 16);
        float mloc = fmaxf(fmaxf(mv.x, mv.y), fmaxf(mv.z, mv.w));
        float sca = __expf(((lane >> 4) ? mv.y : mv.x) - mloc);
        float scb = __expf(((lane >> 4) ? mv.w : mv.z) - mloc);

        // out column t-1 (redundant on all CTAs, lane0, hidden under ldcg)
        if (lane == 0) {
            float4 sv = *(float4*)(sm + SM_S_OFF + p * 128 + w * 16);
            float ey = __expf(mv.y - mloc), ew = __expf(mv.w - mloc);
            float ps = sca * sv.x + ey * sv.y + scb * sv.z + ew * sv.w;
            sm_out[w * 256 + (t - 1)] = mloc + __logf(ps);
        }

        // stage scaled E into padded SMEM row w
        {
            char* edst = sm + E_OFF + w * (ESTR * 2);
            __half2 h2a = __half2half2(__float2half_rn(sca));
            __half2 h2b = __half2half2(__float2half_rn(scb));
            __half2* hp0 = (__half2*)&er0;
            __half2* hp1 = (__half2*)&er1;
            #pragma unroll
            for (int z = 0; z < 4; z++) { hp0[z] = __hmul2(hp0[z], h2a); hp1[z] = __hmul2(hp1[z], h2b); }
            *(uint4*)(edst + lane * 16)        = er0;
            *(uint4*)(edst + (lane + 32) * 16) = er1;
        }
        __syncthreads();

        // HMMA: m16 x n8 x K512 — 8 independent accumulator chains (depth 4)
        float ac[8][4];
        #pragma unroll
        for (int ci = 0; ci < 8; ci++)
            #pragma unroll
            for (int z = 0; z < 4; z++) ac[ci][z] = 0.f;
        #pragma unroll
        for (int kk = 0; kk < 32; kk += 2) {
            const int ci = (kk >> 1) & 3;
            uint32_t b0, b1, c0, c1;
            ldsm4(b0, b1, c0, c1, b_addr4 + (uint32_t)(kk * 32));
            mma16816(ac[ci][0], ac[ci][1], ac[ci][2], ac[ci][3],
                     a[kk][0], a[kk][1], a[kk][2], a[kk][3], b0, b1);
            mma16816(ac[ci + 4][0], ac[ci + 4][1], ac[ci + 4][2], ac[ci + 4][3],
                     a[kk + 1][0], a[kk + 1][1], a[kk + 1][2], a[kk + 1][3], c0, c1);
        }
        float f0, f1, f2, f3;
        {
            float s00 = (ac[0][0] + ac[1][0]) + (ac[2][0] + ac[3][0]);
            float s10 = (ac[4][0] + ac[5][0]) + (ac[6][0] + ac[7][0]);
            float s01 = (ac[0][1] + ac[1][1]) + (ac[2][1] + ac[3][1]);
            float s11 = (ac[4][1] + ac[5][1]) + (ac[6][1] + ac[7][1]);
            float s02 = (ac[0][2] + ac[1][2]) + (ac[2][2] + ac[3][2]);
            float s12 = (ac[4][2] + ac[5][2]) + (ac[6][2] + ac[7][2]);
            float s03 = (ac[0][3] + ac[1][3]) + (ac[2][3] + ac[3][3]);
            float s13 = (ac[4][3] + ac[5][3]) + (ac[6][3] + ac[7][3]);
            f0 = s00 + s10; f1 = s01 + s11; f2 = s02 + s12; f3 = s03 + s13;
        }

        // stash m-tile partials
        {
            float* bw = &buf[w * 162];
            int rr = lane >> 2, c = (lane & 3) * 2;
            *(float2*)&bw[rr * 10 + c]       = make_float2(f0, f1);
            *(float2*)&bw[(rr + 8) * 10 + c] = make_float2(f2, f3);
        }
        __syncthreads();

        // epilogue (prob space): t_i = C_i * em_i; dual interleaved reduction
        {
            int til = lane >> 2, rb = (lane & 3) * 4;
            const float* bp = &buf[til * 162 + w];
            float t0 = bp[(rb + 0) * 10] * et.x;
            float t1 = bp[(rb + 1) * 10] * et.y;
            float t2 = bp[(rb + 2) * 10] * et.z;
            float t3 = bp[(rb + 3) * 10] * et.w;
            float tm = fmaxf(fmaxf(t0, t1), fmaxf(t2, t3));
            float sr = (t0 + t1) + (t2 + t3);
            #pragma unroll
            for (int o = 16; o > 0; o >>= 1) {
                tm = fmaxf(tm, __shfl_xor_sync(0xffffffffu, tm, o));
                sr += __shfl_xor_sync(0xffffffffu, sr, o);
            }
            float r = __fdividef(1.f, tm);
            float e0 = t0 * r, e1 = t1 * r, e2 = t2 * r, e3 = t3 * r;
            union { __half2 h[2]; uint2 uu; } cv;
            cv.h[0] = __floats2half2_rn(e0, e1);
            cv.h[1] = __floats2half2_rn(e2, e3);
            __stcg((uint2*)&gEh[q][gb][j * MI + lane * 4], cv.uu);
            if (lane == 0) {
                float mpub = mloc + __logf(tm);
                float spub = sr * r;
                uint32_t la = SMM + (q * 8 + w) * 16 + j * 4;
                #pragma unroll
                for (int rr = 0; rr < GI; rr++) dsmem_st_ms(la, (uint32_t)rr, mpub, spub);
            }
        }

        CLUSTER_ARRIVE();
    }

    // final column + flush (j == 3 owns the output write)
    CLUSTER_WAIT();
    if (j == 3) {
        if (tid < NBg) {
            float4 mv = *(float4*)(sm + SM_M_OFF + 128 + tid * 16);
            float4 sv = *(float4*)(sm + SM_S_OFF + 128 + tid * 16);
            float mb = fmaxf(fmaxf(mv.x, mv.y), fmaxf(mv.z, mv.w));
            float ss = __expf(mv.x - mb) * sv.x + __expf(mv.y - mb) * sv.y
                     + __expf(mv.z - mb) * sv.z + __expf(mv.w - mb) * sv.w;
            sm_out[tid * 256 + 255] = mb + __logf(ss);
        }
        __syncthreads();
        // flush row w (coalesced float4)
        const float4* orow = (const float4*)(sm_out + w * 256);
        float4* dst = (float4*)&out[gb * TLEN];
        #pragma unroll
        for (int z = 0; z < 2; z++) dst[lane + 32 * z] = orow[lane + 32 * z];
    }
}

// ---------------- launch ----------------
extern "C" void kernel_launch(void* const* d_in, const int* in_sizes, int n_in,
                              void* d_out, int out_size) {
    const int*   batch = (const int*)d_in[0];
    const float* em    = (const float*)d_in[1];
    const float* tr    = (const float*)d_in[2];
    const float* pr    = (const float*)d_in[3];
    float* out = (float*)d_out;

    cudaFuncSetAttribute(forward_kernel, cudaFuncAttributeMaxDynamicSharedMemorySize, SMEM_TOTAL);

    k_prep<<<NSTATES + 1, 256>>>(em, tr, pr);

    cudaLaunchConfig_t cfg = {};
    cfg.gridDim = dim3(NCTA, 1, 1);
    cfg.blockDim = dim3(NT, 1, 1);
    cfg.dynamicSmemBytes = SMEM_TOTAL;
    cfg.stream = 0;
    cudaLaunchAttribute attrs[1];
    attrs[0].id = cudaLaunchAttributeClusterDimension;
    attrs[0].val.clusterDim.x = GI;
    attrs[0].val.clusterDim.y = 1;
    attrs[0].val.clusterDim.z = 1;
    cfg.attrs = attrs;
    cfg.numAttrs = 1;
    cudaLaunchKernelEx(&cfg, forward_kernel, batch, out);
}

// round 17
// speedup vs baseline: 1.5752x; 1.0630x over previous
#include <cuda_runtime.h>
#include <cuda_fp16.h>
#include <cstdint>

#define NSTATES 512
#define MSYMS   256
#define BATCHN  256
#define TLEN    256

#define GB 32                // batch groups (clusters)
#define GI 4                 // cluster size (i-slices)
#define NBg 8                // batch rows per group
#define MI 128               // states per CTA
#define NCTA (GB*GI)         // 128 CTAs
#define NT 256               // 8 warps

#define ESTR 520             // fp16 row stride (1040B)

// ---- dynamic SMEM layout (bytes) ----
#define BUF_OFF    0                     // 8 tiles x 162 floats = 5184
#define SM_M_OFF   5248                  // float [2][8][4] = 256
#define SM_S_OFF   5504                  // float [2][8][4] = 256
#define P_OFF      5760                  // 128 x 520 fp16 = 133120
#define E_OFF      138880                // 8 x 520 fp16 = 8320
#define SYMS_OFF   147200                // 8 x 256 int = 8192
#define OUT_OFF    155392                // float [8][256] = 8192
#define SMEM_TOTAL 163584

// ---------------- device globals ----------------
__device__ __half gPh[NSTATES * NSTATES];   // column-softmax of transition, fp16
__device__ float  gET[MSYMS * NSTATES];     // emission PROBS transposed [sym][state]
__device__ float  gPr[NSTATES];             // prior PROBS
__device__ __half gEh[2][BATCHN][NSTATES];  // scaled E, fp16, dbl-buffered

// ---------------- PTX helpers ----------------
__device__ __forceinline__ uint32_t smem_u32(const void* p) {
    uint32_t a;
    asm("{ .reg .u64 t; cvta.to.shared.u64 t, %1; cvt.u32.u64 %0, t; }" : "=r"(a) : "l"(p));
    return a;
}
__device__ __forceinline__ uint32_t cluster_rank() {
    uint32_t r; asm("mov.u32 %0, %%cluster_ctarank;" : "=r"(r)); return r;
}
#define CLUSTER_ARRIVE() asm volatile("barrier.cluster.arrive.aligned;" ::: "memory")
#define CLUSTER_WAIT()   asm volatile("barrier.cluster.wait.aligned;"   ::: "memory")

__device__ __forceinline__ void dsmem_st_ms(uint32_t laddr_m, uint32_t rank, float mx, float sx) {
    asm volatile(
        "{\n\t.reg .b32 r;\n\t"
        "mapa.shared::cluster.u32 r, %0, %1;\n\t"
        "st.shared::cluster.f32 [r], %2;\n\t"
        "st.shared::cluster.f32 [r+256], %3;\n\t}"
        :: "r"(laddr_m), "r"(rank), "f"(mx), "f"(sx) : "memory");
}
__device__ __forceinline__ void ldsm4(uint32_t& r0, uint32_t& r1, uint32_t& r2, uint32_t& r3,
                                      uint32_t addr) {
    asm volatile("ldmatrix.sync.aligned.m8n8.x4.shared.b16 {%0,%1,%2,%3}, [%4];"
                 : "=r"(r0), "=r"(r1), "=r"(r2), "=r"(r3) : "r"(addr));
}
__device__ __forceinline__ void mma16816(float& d0, float& d1, float& d2, float& d3,
                                         uint32_t a0, uint32_t a1, uint32_t a2, uint32_t a3,
                                         uint32_t b0, uint32_t b1) {
    asm volatile(
        "mma.sync.aligned.m16n8k16.row.col.f32.f16.f16.f32 "
        "{%0,%1,%2,%3}, {%4,%5,%6,%7}, {%8,%9}, {%0,%1,%2,%3};"
        : "+f"(d0), "+f"(d1), "+f"(d2), "+f"(d3)
        : "r"(a0), "r"(a1), "r"(a2), "r"(a3), "r"(b0), "r"(b1));
}

// ---------------- fused prep kernel ----------------
__global__ void k_prep(const float* __restrict__ em, const float* __restrict__ tr,
                       const float* __restrict__ pr) {
    __shared__ float red[256];
    const int blk = blockIdx.x, t = threadIdx.x;

    if (blk < NSTATES) {
        float x = em[blk * MSYMS + t];
        red[t] = x; __syncthreads();
        for (int s = 128; s > 0; s >>= 1) { if (t < s) red[t] = fmaxf(red[t], red[t + s]); __syncthreads(); }
        float m = red[0]; __syncthreads();
        float e = __expf(x - m);
        red[t] = e; __syncthreads();
        for (int s = 128; s > 0; s >>= 1) { if (t < s) red[t] += red[t + s]; __syncthreads(); }
        gET[t * NSTATES + blk] = __fdividef(e, red[0]);
        __syncthreads();

        float x0 = tr[t * NSTATES + blk];
        float x1 = tr[(t + 256) * NSTATES + blk];
        red[t] = fmaxf(x0, x1); __syncthreads();
        for (int s = 128; s > 0; s >>= 1) { if (t < s) red[t] = fmaxf(red[t], red[t + s]); __syncthreads(); }
        float mm = red[0]; __syncthreads();
        red[t] = __expf(x0 - mm) + __expf(x1 - mm); __syncthreads();
        for (int s = 128; s > 0; s >>= 1) { if (t < s) red[t] += red[t + s]; __syncthreads(); }
        float clse = mm + __logf(red[0]);
        gPh[t * NSTATES + blk]         = __float2half_rn(__expf(x0 - clse));
        gPh[(t + 256) * NSTATES + blk] = __float2half_rn(__expf(x1 - clse));
    } else {
        float x0 = pr[t], x1 = pr[t + 256];
        red[t] = fmaxf(x0, x1); __syncthreads();
        for (int s = 128; s > 0; s >>= 1) { if (t < s) red[t] = fmaxf(red[t], red[t + s]); __syncthreads(); }
        float m = red[0]; __syncthreads();
        float e0 = __expf(x0 - m), e1 = __expf(x1 - m);
        red[t] = e0 + e1; __syncthreads();
        for (int s = 128; s > 0; s >>= 1) { if (t < s) red[t] += red[t + s]; __syncthreads(); }
        float inv = __fdividef(1.f, red[0]);
        gPr[t]       = e0 * inv;
        gPr[t + 256] = e1 * inv;
    }
}

// ---------------- forward kernel (4-CTA clusters) ----------------
extern __shared__ char sm_raw[];

__global__ void __launch_bounds__(NT, 1) forward_kernel(const int* __restrict__ batch,
                                                        float* __restrict__ out) {
    char* sm = sm_raw;
    const uint32_t smem_base = smem_u32(sm);
    float* buf    = (float*)(sm + BUF_OFF);
    int*   syms   = (int*)(sm + SYMS_OFF);    // [8][256]
    float* sm_out = (float*)(sm + OUT_OFF);   // [8][256]
    const uint32_t P_base = smem_base + P_OFF;
    const uint32_t E_base = smem_base + E_OFF;
    const uint32_t SMM    = smem_base + SM_M_OFF;

    const int tid  = threadIdx.x;
    const int lane = tid & 31;
    const int w    = tid >> 5;               // warp = m-tile = batch row
    const int g    = blockIdx.x >> 2;        // 0..31 batch group
    const int j    = (int)cluster_rank();    // 0..3 i-slice
    const int gb   = g * NBg + w;            // global batch row for this warp

    // ---------------- prologue ----------------
    #pragma unroll
    for (int it = 0; it < 32; it++) {
        int idx = tid + NT * it;              // 16B chunks
        int row = idx >> 6, c = idx & 63;
        *(uint4*)(sm + P_OFF + row * (ESTR * 2) + c * 16) =
            *(const uint4*)(&gPh[(j * MI + row) * NSTATES] + c * 8);
    }
    for (int idx = tid; idx < NBg * TLEN; idx += NT)
        syms[idx] = batch[(g * NBg + (idx >> 8)) * TLEN + (idx & 255)];
    __syncthreads();

    // A fragments resident in registers: warp w = m-tile w, full K=512
    uint32_t a[32][4];
    {
        const int arow  = w * 16 + (lane & 15);
        const int akoff = (lane >> 4) * 8;
        #pragma unroll
        for (int kk = 0; kk < 32; kk++) {
            uint32_t addr = P_base + (uint32_t)((arow * ESTR + kk * 16 + akoff) * 2);
            ldsm4(a[kk][0], a[kk][1], a[kk][2], a[kk][3], addr);
        }
    }
    // B ldmatrix x4 per-thread address
    const uint32_t b_addr4 = E_base + (uint32_t)(((lane & 7) * ESTR + (lane >> 3) * 8) * 2);

    // ---------------- step 0 (prob space) ----------------
    {
        int sy = syms[w * TLEN + 0];
        float4 et = *(const float4*)&gET[sy * NSTATES + j * MI + lane * 4];
        float4 pp = *(const float4*)&gPr[j * MI + lane * 4];
        float t0 = et.x * pp.x, t1 = et.y * pp.y, t2 = et.z * pp.z, t3 = et.w * pp.w;
        float tm = fmaxf(fmaxf(t0, t1), fmaxf(t2, t3));
        float sr = (t0 + t1) + (t2 + t3);
        #pragma unroll
        for (int o = 16; o > 0; o >>= 1) {
            tm = fmaxf(tm, __shfl_xor_sync(0xffffffffu, tm, o));
            sr += __shfl_xor_sync(0xffffffffu, sr, o);
        }
        float r = __fdividef(1.f, tm);
        float e0 = t0 * r, e1 = t1 * r, e2 = t2 * r, e3 = t3 * r;
        union { __half2 h[2]; uint2 uu; } cv;
        cv.h[0] = __floats2half2_rn(e0, e1);
        cv.h[1] = __floats2half2_rn(e2, e3);
        __stcg((uint2*)&gEh[0][gb][j * MI + lane * 4], cv.uu);
        if (lane == 0) {
            float mpub = __logf(tm);
            float spub = sr * r;
            uint32_t la = SMM + (0 * 8 + w) * 16 + j * 4;
            #pragma unroll
            for (int rr = 0; rr < GI; rr++) dsmem_st_ms(la, (uint32_t)rr, mpub, spub);
        }
        CLUSTER_ARRIVE();
    }

    // ---------------- main loop ----------------
    for (int t = 1; t < TLEN; ++t) {
        const int p = (t - 1) & 1, q = t & 1;

        // prefetch before the wait (emission PROBS for this thread's 4 states)
        int sy = syms[w * TLEN + t];
        float4 et = *(const float4*)&gET[sy * NSTATES + j * MI + lane * 4];

        CLUSTER_WAIT();

        // E raw loads (L2) — issue first, longest latency
        const __half* esrc = &gEh[p][gb][0];
        uint4 er0 = __ldcg((const uint4*)(esrc + lane * 8));
        uint4 er1 = __ldcg((const uint4*)(esrc + (lane + 32) * 8));

        // per-thread stats for row w (16B LDS)
        float4 mv = *(float4*)(sm + SM_M_OFF + p * 128 + w * 16);
        float mloc = fmaxf(fmaxf(mv.x, mv.y), fmaxf(mv.z, mv.w));
        float sca = __expf(((lane >> 4) ? mv.y : mv.x) - mloc);
        float scb = __expf(((lane >> 4) ? mv.w : mv.z) - mloc);

        // out column t-1 (redundant on all CTAs, lane0, hidden under ldcg)
        if (lane == 0) {
            float4 sv = *(float4*)(sm + SM_S_OFF + p * 128 + w * 16);
            float ey = __expf(mv.y - mloc), ew = __expf(mv.w - mloc);
            float ps = sca * sv.x + ey * sv.y + scb * sv.z + ew * sv.w;
            sm_out[w * 256 + (t - 1)] = mloc + __logf(ps);
        }

        // stage scaled E into padded SMEM row w
        {
            char* edst = sm + E_OFF + w * (ESTR * 2);
            __half2 h2a = __half2half2(__float2half_rn(sca));
            __half2 h2b = __half2half2(__float2half_rn(scb));
            __half2* hp0 = (__half2*)&er0;
            __half2* hp1 = (__half2*)&er1;
            #pragma unroll
            for (int z = 0; z < 4; z++) { hp0[z] = __hmul2(hp0[z], h2a); hp1[z] = __hmul2(hp1[z], h2b); }
            *(uint4*)(edst + lane * 16)        = er0;
            *(uint4*)(edst + (lane + 32) * 16) = er1;
        }
        __syncthreads();

        // HMMA: m16 x n8 x K512 — 2 accumulator chains, depth-1 ldsm prefetch
        float aA0 = 0.f, aA1 = 0.f, aA2 = 0.f, aA3 = 0.f;
        float aB0 = 0.f, aB1 = 0.f, aB2 = 0.f, aB3 = 0.f;
        {
            uint32_t b0, b1, c0, c1;       // current fragments
            uint32_t n0, n1, n2, n3;       // next fragments
            ldsm4(b0, b1, c0, c1, b_addr4);
            #pragma unroll
            for (int kk = 0; kk < 32; kk += 2) {
                if (kk + 2 < 32)
                    ldsm4(n0, n1, n2, n3, b_addr4 + (uint32_t)((kk + 2) * 32));
                mma16816(aA0, aA1, aA2, aA3, a[kk][0], a[kk][1], a[kk][2], a[kk][3], b0, b1);
                mma16816(aB0, aB1, aB2, aB3, a[kk+1][0], a[kk+1][1], a[kk+1][2], a[kk+1][3], c0, c1);
                b0 = n0; b1 = n1; c0 = n2; c1 = n3;
            }
        }
        float f0 = aA0 + aB0, f1 = aA1 + aB1, f2 = aA2 + aB2, f3 = aA3 + aB3;

        // stash m-tile partials
        {
            float* bw = &buf[w * 162];
            int rr = lane >> 2, c = (lane & 3) * 2;
            *(float2*)&bw[rr * 10 + c]       = make_float2(f0, f1);
            *(float2*)&bw[(rr + 8) * 10 + c] = make_float2(f2, f3);
        }
        __syncthreads();

        // epilogue (prob space): t_i = C_i * em_i; dual interleaved reduction
        {
            int til = lane >> 2, rb = (lane & 3) * 4;
            const float* bp = &buf[til * 162 + w];
            float t0 = bp[(rb + 0) * 10] * et.x;
            float t1 = bp[(rb + 1) * 10] * et.y;
            float t2 = bp[(rb + 2) * 10] * et.z;
            float t3 = bp[(rb + 3) * 10] * et.w;
            float tm = fmaxf(fmaxf(t0, t1), fmaxf(t2, t3));
            float sr = (t0 + t1) + (t2 + t3);
            #pragma unroll
            for (int o = 16; o > 0; o >>= 1) {
                tm = fmaxf(tm, __shfl_xor_sync(0xffffffffu, tm, o));
                sr += __shfl_xor_sync(0xffffffffu, sr, o);
            }
            float r = __fdividef(1.f, tm);
            float e0 = t0 * r, e1 = t1 * r, e2 = t2 * r, e3 = t3 * r;
            union { __half2 h[2]; uint2 uu; } cv;
            cv.h[0] = __floats2half2_rn(e0, e1);
            cv.h[1] = __floats2half2_rn(e2, e3);
            __stcg((uint2*)&gEh[q][gb][j * MI + lane * 4], cv.uu);
            if (lane == 0) {
                float mpub = mloc + __logf(tm);
                float spub = sr * r;
                uint32_t la = SMM + (q * 8 + w) * 16 + j * 4;
                #pragma unroll
                for (int rr = 0; rr < GI; rr++) dsmem_st_ms(la, (uint32_t)rr, mpub, spub);
            }
        }

        CLUSTER_ARRIVE();
    }

    // final column + flush (j == 3 owns the output write)
    CLUSTER_WAIT();
    if (j == 3) {
        if (tid < NBg) {
            float4 mv = *(float4*)(sm + SM_M_OFF + 128 + tid * 16);
            float4 sv = *(float4*)(sm + SM_S_OFF + 128 + tid * 16);
            float mb = fmaxf(fmaxf(mv.x, mv.y), fmaxf(mv.z, mv.w));
            float ss = __expf(mv.x - mb) * sv.x + __expf(mv.y - mb) * sv.y
                     + __expf(mv.z - mb) * sv.z + __expf(mv.w - mb) * sv.w;
            sm_out[tid * 256 + 255] = mb + __logf(ss);
        }
        __syncthreads();
        // flush row w (coalesced float4)
        const float4* orow = (const float4*)(sm_out + w * 256);
        float4* dst = (float4*)&out[gb * TLEN];
        #pragma unroll
        for (int z = 0; z < 2; z++) dst[lane + 32 * z] = orow[lane + 32 * z];
    }
}

// ---------------- launch ----------------
extern "C" void kernel_launch(void* const* d_in, const int* in_sizes, int n_in,
                              void* d_out, int out_size) {
    const int*   batch = (const int*)d_in[0];
    const float* em    = (const float*)d_in[1];
    const float* tr    = (const float*)d_in[2];
    const float* pr    = (const float*)d_in[3];
    float* out = (float*)d_out;

    cudaFuncSetAttribute(forward_kernel, cudaFuncAttributeMaxDynamicSharedMemorySize, SMEM_TOTAL);

    k_prep<<<NSTATES + 1, 256>>>(em, tr, pr);

    cudaLaunchConfig_t cfg = {};
    cfg.gridDim = dim3(NCTA, 1, 1);
    cfg.blockDim = dim3(NT, 1, 1);
    cfg.dynamicSmemBytes = SMEM_TOTAL;
    cfg.stream = 0;
    cudaLaunchAttribute attrs[1];
    attrs[0].id = cudaLaunchAttributeClusterDimension;
    attrs[0].val.clusterDim.x = GI;
    attrs[0].val.clusterDim.y = 1;
    attrs[0].val.clusterDim.z = 1;
    cfg.attrs = attrs;
    cfg.numAttrs = 1;
    cudaLaunchKernelEx(&cfg, forward_kernel, batch, out);
}